// round 3
// baseline (speedup 1.0000x reference)
#include <cuda_runtime.h>

#define N_NODES 100000
#define N_EDGES_MAX 1600000
#define IN_F    256
#define HID_F   128
#define OUT_F   32

// Scratch: __device__ globals (no allocation allowed anywhere).
__device__ float g_h0[(size_t)N_NODES * HID_F];  // x @ W1
__device__ float g_h1[(size_t)N_NODES * HID_F];  // spmm1 out
__device__ float g_h2[(size_t)N_NODES * OUT_F];  // relu(h1) @ W2

// CSR scratch
__device__ int       g_counts[N_NODES];
__device__ int       g_row_ptr[N_NODES + 1];
__device__ int       g_cursor[N_NODES];
__device__ long long g_edges[N_EDGES_MAX];   // packed: low32=col, high32=val bits

// ---------------------------------------------------------------------------
// CSR build
// ---------------------------------------------------------------------------
__global__ void zero_counts_kernel() {
    int i = blockIdx.x * blockDim.x + threadIdx.x;
    if (i < N_NODES) g_counts[i] = 0;
}

__global__ void hist_kernel(const int* __restrict__ rows, int nE) {
    int e = blockIdx.x * blockDim.x + threadIdx.x;
    if (e < nE) atomicAdd(&g_counts[rows[e]], 1);
}

// Single-block exclusive scan of g_counts -> g_row_ptr / g_cursor.
#define SCAN_T 1024
__global__ __launch_bounds__(SCAN_T) void scan_kernel() {
    __shared__ int sums[SCAN_T];
    const int t = threadIdx.x;
    const int CHUNK = (N_NODES + SCAN_T - 1) / SCAN_T;  // 98
    const int s0 = t * CHUNK;
    const int s1 = min(s0 + CHUNK, N_NODES);

    int local = 0;
    for (int i = s0; i < s1; i++) local += g_counts[i];
    sums[t] = local;
    __syncthreads();

    // Hillis-Steele inclusive scan over sums
    for (int off = 1; off < SCAN_T; off <<= 1) {
        int v = (t >= off) ? sums[t - off] : 0;
        __syncthreads();
        sums[t] += v;
        __syncthreads();
    }
    int offset = sums[t] - local;  // exclusive prefix for this thread's chunk

    int running = offset;
    for (int i = s0; i < s1; i++) {
        g_row_ptr[i] = running;
        g_cursor[i]  = running;
        running += g_counts[i];
    }
    if (s0 < N_NODES && s1 == N_NODES) g_row_ptr[N_NODES] = running;
}

__global__ void scatter_kernel(const int* __restrict__ rows,
                               const int* __restrict__ cols,
                               const float* __restrict__ vals,
                               int nE) {
    int e = blockIdx.x * blockDim.x + threadIdx.x;
    if (e >= nE) return;
    int r = rows[e];
    int pos = atomicAdd(&g_cursor[r], 1);
    long long pk = ((long long)__float_as_int(vals[e]) << 32) | (unsigned int)cols[e];
    g_edges[pos] = pk;
}

// ---------------------------------------------------------------------------
// GEMM1: h0[M,128] = x[M,256] @ W1[256,128]
// 128x128 tile, BK=16, 256 threads, 8x8 per-thread microtile.
// ---------------------------------------------------------------------------
__global__ __launch_bounds__(256) void gemm1_kernel(const float* __restrict__ X,
                                                    const float* __restrict__ W1) {
    __shared__ float As[16][128];   // transposed: As[k][m]
    __shared__ float Bs[16][128];   // Bs[k][n]

    const int tid = threadIdx.x;
    const int tx = tid & 15;
    const int ty = tid >> 4;
    const int m0 = blockIdx.x * 128;

    float acc[8][8];
#pragma unroll
    for (int i = 0; i < 8; i++)
#pragma unroll
        for (int j = 0; j < 8; j++) acc[i][j] = 0.f;

    for (int k0 = 0; k0 < IN_F; k0 += 16) {
#pragma unroll
        for (int i = tid; i < 512; i += 256) {
            int r  = i >> 2;
            int c4 = (i & 3) * 4;
            int gm = m0 + r;
            float4 v = make_float4(0.f, 0.f, 0.f, 0.f);
            if (gm < N_NODES)
                v = *(const float4*)(X + (size_t)gm * IN_F + k0 + c4);
            As[c4 + 0][r] = v.x;
            As[c4 + 1][r] = v.y;
            As[c4 + 2][r] = v.z;
            As[c4 + 3][r] = v.w;
        }
#pragma unroll
        for (int i = tid; i < 512; i += 256) {
            int r  = i >> 5;
            int c4 = (i & 31) * 4;
            *(float4*)&Bs[r][c4] = *(const float4*)(W1 + (size_t)(k0 + r) * HID_F + c4);
        }
        __syncthreads();

#pragma unroll
        for (int kk = 0; kk < 16; kk++) {
            float a[8], b[8];
            float4 a0 = *(const float4*)&As[kk][ty * 8];
            float4 a1 = *(const float4*)&As[kk][ty * 8 + 4];
            float4 b0 = *(const float4*)&Bs[kk][tx * 8];
            float4 b1 = *(const float4*)&Bs[kk][tx * 8 + 4];
            a[0] = a0.x; a[1] = a0.y; a[2] = a0.z; a[3] = a0.w;
            a[4] = a1.x; a[5] = a1.y; a[6] = a1.z; a[7] = a1.w;
            b[0] = b0.x; b[1] = b0.y; b[2] = b0.z; b[3] = b0.w;
            b[4] = b1.x; b[5] = b1.y; b[6] = b1.z; b[7] = b1.w;
#pragma unroll
            for (int i = 0; i < 8; i++)
#pragma unroll
                for (int j = 0; j < 8; j++)
                    acc[i][j] = fmaf(a[i], b[j], acc[i][j]);
        }
        __syncthreads();
    }

#pragma unroll
    for (int i = 0; i < 8; i++) {
        int gm = m0 + ty * 8 + i;
        if (gm < N_NODES) {
            float* op = g_h0 + (size_t)gm * HID_F + tx * 8;
            *(float4*)(op + 0) = make_float4(acc[i][0], acc[i][1], acc[i][2], acc[i][3]);
            *(float4*)(op + 4) = make_float4(acc[i][4], acc[i][5], acc[i][6], acc[i][7]);
        }
    }
}

// ---------------------------------------------------------------------------
// SpMM1 gather (F=128): h1[r] = sum_e val[e] * h0[col[e]]
// One warp per row; lane holds float4; single write per row, no atomics.
// ---------------------------------------------------------------------------
__global__ __launch_bounds__(256) void spmm128_csr_kernel() {
    int row = blockIdx.x * 8 + (threadIdx.x >> 5);
    if (row >= N_NODES) return;
    int lane = threadIdx.x & 31;

    int s = g_row_ptr[row];
    int e1 = g_row_ptr[row + 1];

    float4 acc = make_float4(0.f, 0.f, 0.f, 0.f);

    int e = s;
    if (e < e1) {
        long long pk = __ldg(&g_edges[e]);
        while (true) {
            int c  = (int)(unsigned int)(pk & 0xffffffffLL);
            float v = __int_as_float((int)(pk >> 32));
            long long pk_next = 0;
            if (e + 1 < e1) pk_next = __ldg(&g_edges[e + 1]);
            float4 m = *(const float4*)(g_h0 + (size_t)c * HID_F + lane * 4);
            acc.x = fmaf(m.x, v, acc.x);
            acc.y = fmaf(m.y, v, acc.y);
            acc.z = fmaf(m.z, v, acc.z);
            acc.w = fmaf(m.w, v, acc.w);
            if (++e >= e1) break;
            pk = pk_next;
        }
    }
    *(float4*)(g_h1 + (size_t)row * HID_F + lane * 4) = acc;
}

// ---------------------------------------------------------------------------
// GEMM2: g_h2[M,32] = relu(g_h1)[M,128] @ W2[128,32]
// ---------------------------------------------------------------------------
__global__ __launch_bounds__(256) void gemm2_kernel(const float* __restrict__ W2) {
    __shared__ float Ws[HID_F * OUT_F];
    for (int i = threadIdx.x; i < HID_F * OUT_F; i += 256) Ws[i] = W2[i];
    __syncthreads();

    int r = blockIdx.x * 256 + threadIdx.x;
    if (r >= N_NODES) return;

    float acc[OUT_F];
#pragma unroll
    for (int n = 0; n < OUT_F; n++) acc[n] = 0.f;

    const float4* hp = (const float4*)(g_h1 + (size_t)r * HID_F);
#pragma unroll 4
    for (int k4 = 0; k4 < HID_F / 4; k4++) {
        float4 h = hp[k4];
        h.x = fmaxf(h.x, 0.f);
        h.y = fmaxf(h.y, 0.f);
        h.z = fmaxf(h.z, 0.f);
        h.w = fmaxf(h.w, 0.f);
        int k = k4 * 4;
        float hh[4] = {h.x, h.y, h.z, h.w};
#pragma unroll
        for (int dk = 0; dk < 4; dk++) {
#pragma unroll
            for (int n = 0; n < OUT_F; n += 4) {
                float4 w = *(const float4*)&Ws[(k + dk) * OUT_F + n];
                acc[n + 0] = fmaf(hh[dk], w.x, acc[n + 0]);
                acc[n + 1] = fmaf(hh[dk], w.y, acc[n + 1]);
                acc[n + 2] = fmaf(hh[dk], w.z, acc[n + 2]);
                acc[n + 3] = fmaf(hh[dk], w.w, acc[n + 3]);
            }
        }
    }

    float* op = g_h2 + (size_t)r * OUT_F;
#pragma unroll
    for (int n = 0; n < OUT_F; n += 4)
        *(float4*)(op + n) = make_float4(acc[n], acc[n + 1], acc[n + 2], acc[n + 3]);
}

// ---------------------------------------------------------------------------
// SpMM2 gather (F=32): out[r] = sum_e val[e] * h2[col[e]]
// 8 lanes per row (each lane one float4); 32 rows per 256-thread block.
// ---------------------------------------------------------------------------
__global__ __launch_bounds__(256) void spmm32_csr_kernel(float* __restrict__ out) {
    int row = blockIdx.x * 32 + (threadIdx.x >> 3);
    if (row >= N_NODES) return;
    int lane = threadIdx.x & 7;

    int s = g_row_ptr[row];
    int e1 = g_row_ptr[row + 1];

    float4 acc = make_float4(0.f, 0.f, 0.f, 0.f);

    int e = s;
    if (e < e1) {
        long long pk = __ldg(&g_edges[e]);
        while (true) {
            int c  = (int)(unsigned int)(pk & 0xffffffffLL);
            float v = __int_as_float((int)(pk >> 32));
            long long pk_next = 0;
            if (e + 1 < e1) pk_next = __ldg(&g_edges[e + 1]);
            float4 m = *(const float4*)(g_h2 + (size_t)c * OUT_F + lane * 4);
            acc.x = fmaf(m.x, v, acc.x);
            acc.y = fmaf(m.y, v, acc.y);
            acc.z = fmaf(m.z, v, acc.z);
            acc.w = fmaf(m.w, v, acc.w);
            if (++e >= e1) break;
            pk = pk_next;
        }
    }
    *(float4*)(out + (size_t)row * OUT_F + lane * 4) = acc;
}

// ---------------------------------------------------------------------------
// Launch
// Inputs (metadata order): x, adj_rows, adj_cols, adj_vals, W1, W2
// ---------------------------------------------------------------------------
extern "C" void kernel_launch(void* const* d_in, const int* in_sizes, int n_in,
                              void* d_out, int out_size) {
    const float* x    = (const float*)d_in[0];
    const int*   rows = (const int*)d_in[1];
    const int*   cols = (const int*)d_in[2];
    const float* vals = (const float*)d_in[3];
    const float* W1   = (const float*)d_in[4];
    const float* W2   = (const float*)d_in[5];
    float* out = (float*)d_out;

    const int nE = in_sizes[1];

    // --- CSR build (overlaps conceptually with gemm1; stream-serial is fine) ---
    zero_counts_kernel<<<(N_NODES + 255) / 256, 256>>>();
    hist_kernel<<<(nE + 255) / 256, 256>>>(rows, nE);
    scan_kernel<<<1, SCAN_T>>>();
    scatter_kernel<<<(nE + 255) / 256, 256>>>(rows, cols, vals, nE);

    // GEMM1: x @ W1 -> h0
    gemm1_kernel<<<(N_NODES + 127) / 128, 256>>>(x, W1);

    // SpMM1: h1 = A_hat @ h0  (gather, no atomics)
    spmm128_csr_kernel<<<(N_NODES + 7) / 8, 256>>>();

    // GEMM2: h2 = relu(h1) @ W2
    gemm2_kernel<<<(N_NODES + 255) / 256, 256>>>(W2);

    // SpMM2: out = A_hat @ h2  (gather, no atomics)
    spmm32_csr_kernel<<<(N_NODES + 31) / 32, 256>>>(out);
}

// round 4
// speedup vs baseline: 1.0053x; 1.0053x over previous
#include <cuda_runtime.h>

#define N_NODES 100000
#define N_EDGES_MAX 1600000
#define IN_F    256
#define HID_F   128
#define OUT_F   32

// Scratch: __device__ globals (no allocation allowed anywhere).
__device__ float g_h0[(size_t)N_NODES * HID_F];  // x @ W1
__device__ float g_h1[(size_t)N_NODES * HID_F];  // spmm1 out
__device__ float g_h2[(size_t)N_NODES * OUT_F];  // relu(h1) @ W2

// CSR scratch
__device__ int       g_counts[N_NODES];
__device__ int       g_row_ptr[N_NODES + 1];
__device__ int       g_cursor[N_NODES];
__device__ long long g_edges[N_EDGES_MAX];   // packed: low32=col, high32=val bits

// ---------------------------------------------------------------------------
// CSR build
// ---------------------------------------------------------------------------
__global__ void zero_counts_kernel() {
    int i = blockIdx.x * blockDim.x + threadIdx.x;
    if (i < N_NODES) g_counts[i] = 0;
}

__global__ void hist_kernel(const int* __restrict__ rows, int nE) {
    int i = blockIdx.x * blockDim.x + threadIdx.x;
    int base = i * 4;
    if (base + 4 <= nE) {
        int4 r4 = *(const int4*)(rows + base);
        atomicAdd(&g_counts[r4.x], 1);
        atomicAdd(&g_counts[r4.y], 1);
        atomicAdd(&g_counts[r4.z], 1);
        atomicAdd(&g_counts[r4.w], 1);
    } else {
        for (int e = base; e < nE; e++) atomicAdd(&g_counts[rows[e]], 1);
    }
}

// Single-block exclusive scan of g_counts -> g_row_ptr / g_cursor.
#define SCAN_T 1024
__global__ __launch_bounds__(SCAN_T) void scan_kernel() {
    __shared__ int sums[SCAN_T];
    const int t = threadIdx.x;
    const int CHUNK = (N_NODES + SCAN_T - 1) / SCAN_T;  // 98
    const int s0 = t * CHUNK;
    const int s1 = min(s0 + CHUNK, N_NODES);

    int local = 0;
    for (int i = s0; i < s1; i++) local += g_counts[i];
    sums[t] = local;
    __syncthreads();

    for (int off = 1; off < SCAN_T; off <<= 1) {
        int v = (t >= off) ? sums[t - off] : 0;
        __syncthreads();
        sums[t] += v;
        __syncthreads();
    }
    int offset = sums[t] - local;

    int running = offset;
    for (int i = s0; i < s1; i++) {
        g_row_ptr[i] = running;
        g_cursor[i]  = running;
        running += g_counts[i];
    }
    if (s0 < N_NODES && s1 == N_NODES) g_row_ptr[N_NODES] = running;
}

__global__ void scatter_kernel(const int* __restrict__ rows,
                               const int* __restrict__ cols,
                               const float* __restrict__ vals,
                               int nE) {
    int e = blockIdx.x * blockDim.x + threadIdx.x;
    if (e >= nE) return;
    int r = rows[e];
    int pos = atomicAdd(&g_cursor[r], 1);
    long long pk = ((long long)__float_as_int(vals[e]) << 32) | (unsigned int)cols[e];
    g_edges[pos] = pk;
}

// ---------------------------------------------------------------------------
// GEMM1: h0[M,128] = x[M,256] @ W1[256,128]
// 128x128 tile, BK=16, 256 threads, 8x8 per-thread microtile.
// ---------------------------------------------------------------------------
__global__ __launch_bounds__(256) void gemm1_kernel(const float* __restrict__ X,
                                                    const float* __restrict__ W1) {
    __shared__ float As[16][128];
    __shared__ float Bs[16][128];

    const int tid = threadIdx.x;
    const int tx = tid & 15;
    const int ty = tid >> 4;
    const int m0 = blockIdx.x * 128;

    float acc[8][8];
#pragma unroll
    for (int i = 0; i < 8; i++)
#pragma unroll
        for (int j = 0; j < 8; j++) acc[i][j] = 0.f;

    for (int k0 = 0; k0 < IN_F; k0 += 16) {
#pragma unroll
        for (int i = tid; i < 512; i += 256) {
            int r  = i >> 2;
            int c4 = (i & 3) * 4;
            int gm = m0 + r;
            float4 v = make_float4(0.f, 0.f, 0.f, 0.f);
            if (gm < N_NODES)
                v = *(const float4*)(X + (size_t)gm * IN_F + k0 + c4);
            As[c4 + 0][r] = v.x;
            As[c4 + 1][r] = v.y;
            As[c4 + 2][r] = v.z;
            As[c4 + 3][r] = v.w;
        }
#pragma unroll
        for (int i = tid; i < 512; i += 256) {
            int r  = i >> 5;
            int c4 = (i & 31) * 4;
            *(float4*)&Bs[r][c4] = *(const float4*)(W1 + (size_t)(k0 + r) * HID_F + c4);
        }
        __syncthreads();

#pragma unroll
        for (int kk = 0; kk < 16; kk++) {
            float a[8], b[8];
            float4 a0 = *(const float4*)&As[kk][ty * 8];
            float4 a1 = *(const float4*)&As[kk][ty * 8 + 4];
            float4 b0 = *(const float4*)&Bs[kk][tx * 8];
            float4 b1 = *(const float4*)&Bs[kk][tx * 8 + 4];
            a[0] = a0.x; a[1] = a0.y; a[2] = a0.z; a[3] = a0.w;
            a[4] = a1.x; a[5] = a1.y; a[6] = a1.z; a[7] = a1.w;
            b[0] = b0.x; b[1] = b0.y; b[2] = b0.z; b[3] = b0.w;
            b[4] = b1.x; b[5] = b1.y; b[6] = b1.z; b[7] = b1.w;
#pragma unroll
            for (int i = 0; i < 8; i++)
#pragma unroll
                for (int j = 0; j < 8; j++)
                    acc[i][j] = fmaf(a[i], b[j], acc[i][j]);
        }
        __syncthreads();
    }

#pragma unroll
    for (int i = 0; i < 8; i++) {
        int gm = m0 + ty * 8 + i;
        if (gm < N_NODES) {
            float* op = g_h0 + (size_t)gm * HID_F + tx * 8;
            *(float4*)(op + 0) = make_float4(acc[i][0], acc[i][1], acc[i][2], acc[i][3]);
            *(float4*)(op + 4) = make_float4(acc[i][4], acc[i][5], acc[i][6], acc[i][7]);
        }
    }
}

// ---------------------------------------------------------------------------
// SpMM1 gather (F=128): h1[r] = sum_e val[e] * h0[col[e]]
// Warp per row, 4-way unrolled edge loop for MLP.
// ---------------------------------------------------------------------------
__global__ __launch_bounds__(256) void spmm128_csr_kernel() {
    int row = blockIdx.x * 8 + (threadIdx.x >> 5);
    if (row >= N_NODES) return;
    int lane = threadIdx.x & 31;

    int e  = __ldg(&g_row_ptr[row]);
    int e1 = __ldg(&g_row_ptr[row + 1]);

    float4 acc = make_float4(0.f, 0.f, 0.f, 0.f);

    for (; e + 4 <= e1; e += 4) {
        long long p0 = __ldg(&g_edges[e + 0]);
        long long p1 = __ldg(&g_edges[e + 1]);
        long long p2 = __ldg(&g_edges[e + 2]);
        long long p3 = __ldg(&g_edges[e + 3]);
        const float4* r0 = (const float4*)(g_h0 + (size_t)(unsigned int)(p0 & 0xffffffffLL) * HID_F) + lane;
        const float4* r1 = (const float4*)(g_h0 + (size_t)(unsigned int)(p1 & 0xffffffffLL) * HID_F) + lane;
        const float4* r2 = (const float4*)(g_h0 + (size_t)(unsigned int)(p2 & 0xffffffffLL) * HID_F) + lane;
        const float4* r3 = (const float4*)(g_h0 + (size_t)(unsigned int)(p3 & 0xffffffffLL) * HID_F) + lane;
        float4 m0 = *r0;
        float4 m1 = *r1;
        float4 m2 = *r2;
        float4 m3 = *r3;
        float v0 = __int_as_float((int)(p0 >> 32));
        float v1 = __int_as_float((int)(p1 >> 32));
        float v2 = __int_as_float((int)(p2 >> 32));
        float v3 = __int_as_float((int)(p3 >> 32));
        acc.x = fmaf(m0.x, v0, acc.x); acc.y = fmaf(m0.y, v0, acc.y);
        acc.z = fmaf(m0.z, v0, acc.z); acc.w = fmaf(m0.w, v0, acc.w);
        acc.x = fmaf(m1.x, v1, acc.x); acc.y = fmaf(m1.y, v1, acc.y);
        acc.z = fmaf(m1.z, v1, acc.z); acc.w = fmaf(m1.w, v1, acc.w);
        acc.x = fmaf(m2.x, v2, acc.x); acc.y = fmaf(m2.y, v2, acc.y);
        acc.z = fmaf(m2.z, v2, acc.z); acc.w = fmaf(m2.w, v2, acc.w);
        acc.x = fmaf(m3.x, v3, acc.x); acc.y = fmaf(m3.y, v3, acc.y);
        acc.z = fmaf(m3.z, v3, acc.z); acc.w = fmaf(m3.w, v3, acc.w);
    }
    for (; e < e1; e++) {
        long long pk = __ldg(&g_edges[e]);
        int c  = (int)(unsigned int)(pk & 0xffffffffLL);
        float v = __int_as_float((int)(pk >> 32));
        float4 m = *((const float4*)(g_h0 + (size_t)c * HID_F) + lane);
        acc.x = fmaf(m.x, v, acc.x);
        acc.y = fmaf(m.y, v, acc.y);
        acc.z = fmaf(m.z, v, acc.z);
        acc.w = fmaf(m.w, v, acc.w);
    }
    *((float4*)(g_h1 + (size_t)row * HID_F) + lane) = acc;
}

// ---------------------------------------------------------------------------
// GEMM2: g_h2[M,32] = relu(g_h1)[M,128] @ W2[128,32]
// ---------------------------------------------------------------------------
__global__ __launch_bounds__(256) void gemm2_kernel(const float* __restrict__ W2) {
    __shared__ float Ws[HID_F * OUT_F];
    for (int i = threadIdx.x; i < HID_F * OUT_F; i += 256) Ws[i] = W2[i];
    __syncthreads();

    int r = blockIdx.x * 256 + threadIdx.x;
    if (r >= N_NODES) return;

    float acc[OUT_F];
#pragma unroll
    for (int n = 0; n < OUT_F; n++) acc[n] = 0.f;

    const float4* hp = (const float4*)(g_h1 + (size_t)r * HID_F);
#pragma unroll 4
    for (int k4 = 0; k4 < HID_F / 4; k4++) {
        float4 h = hp[k4];
        h.x = fmaxf(h.x, 0.f);
        h.y = fmaxf(h.y, 0.f);
        h.z = fmaxf(h.z, 0.f);
        h.w = fmaxf(h.w, 0.f);
        int k = k4 * 4;
        float hh[4] = {h.x, h.y, h.z, h.w};
#pragma unroll
        for (int dk = 0; dk < 4; dk++) {
#pragma unroll
            for (int n = 0; n < OUT_F; n += 4) {
                float4 w = *(const float4*)&Ws[(k + dk) * OUT_F + n];
                acc[n + 0] = fmaf(hh[dk], w.x, acc[n + 0]);
                acc[n + 1] = fmaf(hh[dk], w.y, acc[n + 1]);
                acc[n + 2] = fmaf(hh[dk], w.z, acc[n + 2]);
                acc[n + 3] = fmaf(hh[dk], w.w, acc[n + 3]);
            }
        }
    }

    float* op = g_h2 + (size_t)r * OUT_F;
#pragma unroll
    for (int n = 0; n < OUT_F; n += 4)
        *(float4*)(op + n) = make_float4(acc[n], acc[n + 1], acc[n + 2], acc[n + 3]);
}

// ---------------------------------------------------------------------------
// SpMM2 gather (F=32): out[r] = sum_e val[e] * h2[col[e]]
// 8 lanes per row, 4-way unrolled for MLP.
// ---------------------------------------------------------------------------
__global__ __launch_bounds__(256) void spmm32_csr_kernel(float* __restrict__ out) {
    int row = blockIdx.x * 32 + (threadIdx.x >> 3);
    if (row >= N_NODES) return;
    int lane = threadIdx.x & 7;

    int e  = __ldg(&g_row_ptr[row]);
    int e1 = __ldg(&g_row_ptr[row + 1]);

    float4 acc = make_float4(0.f, 0.f, 0.f, 0.f);

    for (; e + 4 <= e1; e += 4) {
        long long p0 = __ldg(&g_edges[e + 0]);
        long long p1 = __ldg(&g_edges[e + 1]);
        long long p2 = __ldg(&g_edges[e + 2]);
        long long p3 = __ldg(&g_edges[e + 3]);
        float4 m0 = *((const float4*)(g_h2 + (size_t)(unsigned int)(p0 & 0xffffffffLL) * OUT_F) + lane);
        float4 m1 = *((const float4*)(g_h2 + (size_t)(unsigned int)(p1 & 0xffffffffLL) * OUT_F) + lane);
        float4 m2 = *((const float4*)(g_h2 + (size_t)(unsigned int)(p2 & 0xffffffffLL) * OUT_F) + lane);
        float4 m3 = *((const float4*)(g_h2 + (size_t)(unsigned int)(p3 & 0xffffffffLL) * OUT_F) + lane);
        float v0 = __int_as_float((int)(p0 >> 32));
        float v1 = __int_as_float((int)(p1 >> 32));
        float v2 = __int_as_float((int)(p2 >> 32));
        float v3 = __int_as_float((int)(p3 >> 32));
        acc.x = fmaf(m0.x, v0, acc.x); acc.y = fmaf(m0.y, v0, acc.y);
        acc.z = fmaf(m0.z, v0, acc.z); acc.w = fmaf(m0.w, v0, acc.w);
        acc.x = fmaf(m1.x, v1, acc.x); acc.y = fmaf(m1.y, v1, acc.y);
        acc.z = fmaf(m1.z, v1, acc.z); acc.w = fmaf(m1.w, v1, acc.w);
        acc.x = fmaf(m2.x, v2, acc.x); acc.y = fmaf(m2.y, v2, acc.y);
        acc.z = fmaf(m2.z, v2, acc.z); acc.w = fmaf(m2.w, v2, acc.w);
        acc.x = fmaf(m3.x, v3, acc.x); acc.y = fmaf(m3.y, v3, acc.y);
        acc.z = fmaf(m3.z, v3, acc.z); acc.w = fmaf(m3.w, v3, acc.w);
    }
    for (; e < e1; e++) {
        long long pk = __ldg(&g_edges[e]);
        int c  = (int)(unsigned int)(pk & 0xffffffffLL);
        float v = __int_as_float((int)(pk >> 32));
        float4 m = *((const float4*)(g_h2 + (size_t)c * OUT_F) + lane);
        acc.x = fmaf(m.x, v, acc.x);
        acc.y = fmaf(m.y, v, acc.y);
        acc.z = fmaf(m.z, v, acc.z);
        acc.w = fmaf(m.w, v, acc.w);
    }
    *((float4*)(out + (size_t)row * OUT_F) + lane) = acc;
}

// ---------------------------------------------------------------------------
// Launch
// Inputs (metadata order): x, adj_rows, adj_cols, adj_vals, W1, W2
// ---------------------------------------------------------------------------
extern "C" void kernel_launch(void* const* d_in, const int* in_sizes, int n_in,
                              void* d_out, int out_size) {
    const float* x    = (const float*)d_in[0];
    const int*   rows = (const int*)d_in[1];
    const int*   cols = (const int*)d_in[2];
    const float* vals = (const float*)d_in[3];
    const float* W1   = (const float*)d_in[4];
    const float* W2   = (const float*)d_in[5];
    float* out = (float*)d_out;

    const int nE = in_sizes[1];

    // --- CSR build ---
    zero_counts_kernel<<<(N_NODES + 255) / 256, 256>>>();
    hist_kernel<<<(nE / 4 + 255) / 256, 256>>>(rows, nE);
    scan_kernel<<<1, SCAN_T>>>();
    scatter_kernel<<<(nE + 255) / 256, 256>>>(rows, cols, vals, nE);

    // GEMM1: x @ W1 -> h0
    gemm1_kernel<<<(N_NODES + 127) / 128, 256>>>(x, W1);

    // SpMM1: h1 = A_hat @ h0  (gather, no atomics, MLP=4)
    spmm128_csr_kernel<<<(N_NODES + 7) / 8, 256>>>();

    // GEMM2: h2 = relu(h1) @ W2
    gemm2_kernel<<<(N_NODES + 255) / 256, 256>>>(W2);

    // SpMM2: out = A_hat @ h2  (gather, no atomics, MLP=4)
    spmm32_csr_kernel<<<(N_NODES + 31) / 32, 256>>>(out);
}

// round 5
// speedup vs baseline: 1.0493x; 1.0438x over previous
#include <cuda_runtime.h>
#include <cuda_fp16.h>

#define N_NODES 100000
#define N_EDGES_MAX 1600000
#define IN_F    256
#define HID_F   128
#define OUT_F   32

// Scratch: __device__ globals (no allocation allowed anywhere).
__device__ __half g_h0h[(size_t)N_NODES * HID_F];  // x @ W1   (fp16 payload)
__device__ float  g_h1[(size_t)N_NODES * HID_F];   // spmm1 out (fp32)
__device__ __half g_h2h[(size_t)N_NODES * OUT_F];  // relu(h1) @ W2 (fp16 payload)

// CSR scratch
__device__ int       g_counts[N_NODES];
__device__ int       g_row_ptr[N_NODES + 1];
__device__ int       g_cursor[N_NODES];
__device__ long long g_edges[N_EDGES_MAX];   // packed: low32=col, high32=val bits

// ---------------------------------------------------------------------------
// CSR build
// ---------------------------------------------------------------------------
__global__ void zero_counts_kernel() {
    int i = blockIdx.x * blockDim.x + threadIdx.x;
    if (i < N_NODES) g_counts[i] = 0;
}

__global__ void hist_kernel(const int* __restrict__ rows, int nE) {
    int i = blockIdx.x * blockDim.x + threadIdx.x;
    int base = i * 4;
    if (base + 4 <= nE) {
        int4 r4 = *(const int4*)(rows + base);
        atomicAdd(&g_counts[r4.x], 1);
        atomicAdd(&g_counts[r4.y], 1);
        atomicAdd(&g_counts[r4.z], 1);
        atomicAdd(&g_counts[r4.w], 1);
    } else {
        for (int e = base; e < nE; e++) atomicAdd(&g_counts[rows[e]], 1);
    }
}

// Single-block exclusive scan of g_counts -> g_row_ptr / g_cursor.
#define SCAN_T 1024
__global__ __launch_bounds__(SCAN_T) void scan_kernel() {
    __shared__ int sums[SCAN_T];
    const int t = threadIdx.x;
    const int CHUNK = (N_NODES + SCAN_T - 1) / SCAN_T;  // 98
    const int s0 = t * CHUNK;
    const int s1 = min(s0 + CHUNK, N_NODES);

    int local = 0;
    for (int i = s0; i < s1; i++) local += g_counts[i];
    sums[t] = local;
    __syncthreads();

    for (int off = 1; off < SCAN_T; off <<= 1) {
        int v = (t >= off) ? sums[t - off] : 0;
        __syncthreads();
        sums[t] += v;
        __syncthreads();
    }
    int offset = sums[t] - local;

    int running = offset;
    for (int i = s0; i < s1; i++) {
        g_row_ptr[i] = running;
        g_cursor[i]  = running;
        running += g_counts[i];
    }
    if (s0 < N_NODES && s1 == N_NODES) g_row_ptr[N_NODES] = running;
}

__global__ void scatter_kernel(const int* __restrict__ rows,
                               const int* __restrict__ cols,
                               const float* __restrict__ vals,
                               int nE) {
    int e = blockIdx.x * blockDim.x + threadIdx.x;
    if (e >= nE) return;
    int r = rows[e];
    int pos = atomicAdd(&g_cursor[r], 1);
    long long pk = ((long long)__float_as_int(vals[e]) << 32) | (unsigned int)cols[e];
    g_edges[pos] = pk;
}

// ---------------------------------------------------------------------------
// GEMM1: h0[M,128] = x[M,256] @ W1[256,128], fp32 math, fp16 store.
// 128x128 tile, BK=16, 256 threads, 8x8 per-thread microtile.
// ---------------------------------------------------------------------------
__global__ __launch_bounds__(256) void gemm1_kernel(const float* __restrict__ X,
                                                    const float* __restrict__ W1) {
    __shared__ float As[16][128];
    __shared__ float Bs[16][128];

    const int tid = threadIdx.x;
    const int tx = tid & 15;
    const int ty = tid >> 4;
    const int m0 = blockIdx.x * 128;

    float acc[8][8];
#pragma unroll
    for (int i = 0; i < 8; i++)
#pragma unroll
        for (int j = 0; j < 8; j++) acc[i][j] = 0.f;

    for (int k0 = 0; k0 < IN_F; k0 += 16) {
#pragma unroll
        for (int i = tid; i < 512; i += 256) {
            int r  = i >> 2;
            int c4 = (i & 3) * 4;
            int gm = m0 + r;
            float4 v = make_float4(0.f, 0.f, 0.f, 0.f);
            if (gm < N_NODES)
                v = *(const float4*)(X + (size_t)gm * IN_F + k0 + c4);
            As[c4 + 0][r] = v.x;
            As[c4 + 1][r] = v.y;
            As[c4 + 2][r] = v.z;
            As[c4 + 3][r] = v.w;
        }
#pragma unroll
        for (int i = tid; i < 512; i += 256) {
            int r  = i >> 5;
            int c4 = (i & 31) * 4;
            *(float4*)&Bs[r][c4] = *(const float4*)(W1 + (size_t)(k0 + r) * HID_F + c4);
        }
        __syncthreads();

#pragma unroll
        for (int kk = 0; kk < 16; kk++) {
            float a[8], b[8];
            float4 a0 = *(const float4*)&As[kk][ty * 8];
            float4 a1 = *(const float4*)&As[kk][ty * 8 + 4];
            float4 b0 = *(const float4*)&Bs[kk][tx * 8];
            float4 b1 = *(const float4*)&Bs[kk][tx * 8 + 4];
            a[0] = a0.x; a[1] = a0.y; a[2] = a0.z; a[3] = a0.w;
            a[4] = a1.x; a[5] = a1.y; a[6] = a1.z; a[7] = a1.w;
            b[0] = b0.x; b[1] = b0.y; b[2] = b0.z; b[3] = b0.w;
            b[4] = b1.x; b[5] = b1.y; b[6] = b1.z; b[7] = b1.w;
#pragma unroll
            for (int i = 0; i < 8; i++)
#pragma unroll
                for (int j = 0; j < 8; j++)
                    acc[i][j] = fmaf(a[i], b[j], acc[i][j]);
        }
        __syncthreads();
    }

#pragma unroll
    for (int i = 0; i < 8; i++) {
        int gm = m0 + ty * 8 + i;
        if (gm < N_NODES) {
            __half2 h[4];
#pragma unroll
            for (int j = 0; j < 4; j++)
                h[j] = __floats2half2_rn(acc[i][2 * j], acc[i][2 * j + 1]);
            *(uint4*)(g_h0h + (size_t)gm * HID_F + tx * 8) = *(uint4*)h;
        }
    }
}

// ---------------------------------------------------------------------------
// SpMM1 gather (F=128, fp16 payload): h1[r] = sum_e val[e] * h0[col[e]]
// Warp per row; lane reads 4 halves (uint2); fp32 accumulate; 4-way unroll.
// ---------------------------------------------------------------------------
__device__ __forceinline__ void fma_h4(float4& acc, uint2 m, float v) {
    float2 f0 = __half22float2(*(__half2*)&m.x);
    float2 f1 = __half22float2(*(__half2*)&m.y);
    acc.x = fmaf(f0.x, v, acc.x);
    acc.y = fmaf(f0.y, v, acc.y);
    acc.z = fmaf(f1.x, v, acc.z);
    acc.w = fmaf(f1.y, v, acc.w);
}

__global__ __launch_bounds__(256) void spmm128_csr_kernel() {
    int row = blockIdx.x * 8 + (threadIdx.x >> 5);
    if (row >= N_NODES) return;
    int lane = threadIdx.x & 31;

    int e  = __ldg(&g_row_ptr[row]);
    int e1 = __ldg(&g_row_ptr[row + 1]);

    float4 acc = make_float4(0.f, 0.f, 0.f, 0.f);

    for (; e + 4 <= e1; e += 4) {
        long long p0 = __ldg(&g_edges[e + 0]);
        long long p1 = __ldg(&g_edges[e + 1]);
        long long p2 = __ldg(&g_edges[e + 2]);
        long long p3 = __ldg(&g_edges[e + 3]);
        uint2 m0 = *((const uint2*)(g_h0h + (size_t)(unsigned int)(p0 & 0xffffffffLL) * HID_F) + lane);
        uint2 m1 = *((const uint2*)(g_h0h + (size_t)(unsigned int)(p1 & 0xffffffffLL) * HID_F) + lane);
        uint2 m2 = *((const uint2*)(g_h0h + (size_t)(unsigned int)(p2 & 0xffffffffLL) * HID_F) + lane);
        uint2 m3 = *((const uint2*)(g_h0h + (size_t)(unsigned int)(p3 & 0xffffffffLL) * HID_F) + lane);
        fma_h4(acc, m0, __int_as_float((int)(p0 >> 32)));
        fma_h4(acc, m1, __int_as_float((int)(p1 >> 32)));
        fma_h4(acc, m2, __int_as_float((int)(p2 >> 32)));
        fma_h4(acc, m3, __int_as_float((int)(p3 >> 32)));
    }
    for (; e < e1; e++) {
        long long pk = __ldg(&g_edges[e]);
        int c  = (int)(unsigned int)(pk & 0xffffffffLL);
        uint2 m = *((const uint2*)(g_h0h + (size_t)c * HID_F) + lane);
        fma_h4(acc, m, __int_as_float((int)(pk >> 32)));
    }
    *((float4*)(g_h1 + (size_t)row * HID_F) + lane) = acc;
}

// ---------------------------------------------------------------------------
// GEMM2: g_h2h[M,32] = fp16( relu(g_h1)[M,128] @ W2[128,32] )
// ---------------------------------------------------------------------------
__global__ __launch_bounds__(256) void gemm2_kernel(const float* __restrict__ W2) {
    __shared__ float Ws[HID_F * OUT_F];
    for (int i = threadIdx.x; i < HID_F * OUT_F; i += 256) Ws[i] = W2[i];
    __syncthreads();

    int r = blockIdx.x * 256 + threadIdx.x;
    if (r >= N_NODES) return;

    float acc[OUT_F];
#pragma unroll
    for (int n = 0; n < OUT_F; n++) acc[n] = 0.f;

    const float4* hp = (const float4*)(g_h1 + (size_t)r * HID_F);
#pragma unroll 4
    for (int k4 = 0; k4 < HID_F / 4; k4++) {
        float4 h = hp[k4];
        h.x = fmaxf(h.x, 0.f);
        h.y = fmaxf(h.y, 0.f);
        h.z = fmaxf(h.z, 0.f);
        h.w = fmaxf(h.w, 0.f);
        int k = k4 * 4;
        float hh[4] = {h.x, h.y, h.z, h.w};
#pragma unroll
        for (int dk = 0; dk < 4; dk++) {
#pragma unroll
            for (int n = 0; n < OUT_F; n += 4) {
                float4 w = *(const float4*)&Ws[(k + dk) * OUT_F + n];
                acc[n + 0] = fmaf(hh[dk], w.x, acc[n + 0]);
                acc[n + 1] = fmaf(hh[dk], w.y, acc[n + 1]);
                acc[n + 2] = fmaf(hh[dk], w.z, acc[n + 2]);
                acc[n + 3] = fmaf(hh[dk], w.w, acc[n + 3]);
            }
        }
    }

    __half2 hb[OUT_F / 2];
#pragma unroll
    for (int n = 0; n < OUT_F / 2; n++)
        hb[n] = __floats2half2_rn(acc[2 * n], acc[2 * n + 1]);
    uint4* op = (uint4*)(g_h2h + (size_t)r * OUT_F);
#pragma unroll
    for (int q = 0; q < 4; q++)
        op[q] = ((uint4*)hb)[q];
}

// ---------------------------------------------------------------------------
// SpMM2 gather (F=32, fp16 payload): out[r] = sum_e val[e] * h2[col[e]]
// 8 lanes per row; each lane 4 halves; 4-way unrolled.
// ---------------------------------------------------------------------------
__global__ __launch_bounds__(256) void spmm32_csr_kernel(float* __restrict__ out) {
    int row = blockIdx.x * 32 + (threadIdx.x >> 3);
    if (row >= N_NODES) return;
    int lane = threadIdx.x & 7;

    int e  = __ldg(&g_row_ptr[row]);
    int e1 = __ldg(&g_row_ptr[row + 1]);

    float4 acc = make_float4(0.f, 0.f, 0.f, 0.f);

    for (; e + 4 <= e1; e += 4) {
        long long p0 = __ldg(&g_edges[e + 0]);
        long long p1 = __ldg(&g_edges[e + 1]);
        long long p2 = __ldg(&g_edges[e + 2]);
        long long p3 = __ldg(&g_edges[e + 3]);
        uint2 m0 = *((const uint2*)(g_h2h + (size_t)(unsigned int)(p0 & 0xffffffffLL) * OUT_F) + lane);
        uint2 m1 = *((const uint2*)(g_h2h + (size_t)(unsigned int)(p1 & 0xffffffffLL) * OUT_F) + lane);
        uint2 m2 = *((const uint2*)(g_h2h + (size_t)(unsigned int)(p2 & 0xffffffffLL) * OUT_F) + lane);
        uint2 m3 = *((const uint2*)(g_h2h + (size_t)(unsigned int)(p3 & 0xffffffffLL) * OUT_F) + lane);
        fma_h4(acc, m0, __int_as_float((int)(p0 >> 32)));
        fma_h4(acc, m1, __int_as_float((int)(p1 >> 32)));
        fma_h4(acc, m2, __int_as_float((int)(p2 >> 32)));
        fma_h4(acc, m3, __int_as_float((int)(p3 >> 32)));
    }
    for (; e < e1; e++) {
        long long pk = __ldg(&g_edges[e]);
        int c  = (int)(unsigned int)(pk & 0xffffffffLL);
        uint2 m = *((const uint2*)(g_h2h + (size_t)c * OUT_F) + lane);
        fma_h4(acc, m, __int_as_float((int)(pk >> 32)));
    }
    *((float4*)(out + (size_t)row * OUT_F) + lane) = acc;
}

// ---------------------------------------------------------------------------
// Launch
// Inputs (metadata order): x, adj_rows, adj_cols, adj_vals, W1, W2
// ---------------------------------------------------------------------------
extern "C" void kernel_launch(void* const* d_in, const int* in_sizes, int n_in,
                              void* d_out, int out_size) {
    const float* x    = (const float*)d_in[0];
    const int*   rows = (const int*)d_in[1];
    const int*   cols = (const int*)d_in[2];
    const float* vals = (const float*)d_in[3];
    const float* W1   = (const float*)d_in[4];
    const float* W2   = (const float*)d_in[5];
    float* out = (float*)d_out;

    const int nE = in_sizes[1];

    // --- CSR build ---
    zero_counts_kernel<<<(N_NODES + 255) / 256, 256>>>();
    hist_kernel<<<(nE / 4 + 255) / 256, 256>>>(rows, nE);
    scan_kernel<<<1, SCAN_T>>>();
    scatter_kernel<<<(nE + 255) / 256, 256>>>(rows, cols, vals, nE);

    // GEMM1: x @ W1 -> h0 (fp16 store)
    gemm1_kernel<<<(N_NODES + 127) / 128, 256>>>(x, W1);

    // SpMM1: h1 = A_hat @ h0  (fp16 gather, fp32 accum)
    spmm128_csr_kernel<<<(N_NODES + 7) / 8, 256>>>();

    // GEMM2: h2 = relu(h1) @ W2 (fp16 store)
    gemm2_kernel<<<(N_NODES + 255) / 256, 256>>>(W2);

    // SpMM2: out = A_hat @ h2  (fp16 gather, fp32 accum)
    spmm32_csr_kernel<<<(N_NODES + 31) / 32, 256>>>(out);
}

// round 6
// speedup vs baseline: 1.3610x; 1.2971x over previous
#include <cuda_runtime.h>
#include <cuda_fp16.h>

#define N_NODES 100000
#define N_EDGES_MAX 1600000
#define IN_F    256
#define HID_F   128
#define OUT_F   32

// Scratch: __device__ globals (no allocation allowed anywhere).
__device__ __half g_h0h[(size_t)N_NODES * HID_F];  // x @ W1   (fp16 payload)
__device__ float  g_h1[(size_t)N_NODES * HID_F];   // spmm1 out (fp32)
__device__ __half g_h2h[(size_t)N_NODES * OUT_F];  // relu(h1) @ W2 (fp16 payload)

// CSR scratch
__device__ int       g_counts[N_NODES];
__device__ int       g_row_ptr[N_NODES + 1];
__device__ int       g_cursor[N_NODES];
__device__ long long g_edges[N_EDGES_MAX];   // packed: low32=col, high32=val bits

// ---------------------------------------------------------------------------
// CSR build
// ---------------------------------------------------------------------------
__global__ void zero_counts_kernel() {
    int i = blockIdx.x * blockDim.x + threadIdx.x;
    if (i < N_NODES) g_counts[i] = 0;
}

__global__ void hist_kernel(const int* __restrict__ rows, int nE) {
    int i = blockIdx.x * blockDim.x + threadIdx.x;
    int base = i * 4;
    if (base + 4 <= nE) {
        int4 r4 = *(const int4*)(rows + base);
        atomicAdd(&g_counts[r4.x], 1);
        atomicAdd(&g_counts[r4.y], 1);
        atomicAdd(&g_counts[r4.z], 1);
        atomicAdd(&g_counts[r4.w], 1);
    } else {
        for (int e = base; e < nE; e++) atomicAdd(&g_counts[rows[e]], 1);
    }
}

#define SCAN_T 1024
__global__ __launch_bounds__(SCAN_T) void scan_kernel() {
    __shared__ int sums[SCAN_T];
    const int t = threadIdx.x;
    const int CHUNK = (N_NODES + SCAN_T - 1) / SCAN_T;  // 98
    const int s0 = t * CHUNK;
    const int s1 = min(s0 + CHUNK, N_NODES);

    int local = 0;
    for (int i = s0; i < s1; i++) local += g_counts[i];
    sums[t] = local;
    __syncthreads();

    for (int off = 1; off < SCAN_T; off <<= 1) {
        int v = (t >= off) ? sums[t - off] : 0;
        __syncthreads();
        sums[t] += v;
        __syncthreads();
    }
    int offset = sums[t] - local;

    int running = offset;
    for (int i = s0; i < s1; i++) {
        g_row_ptr[i] = running;
        g_cursor[i]  = running;
        running += g_counts[i];
    }
    if (s0 < N_NODES && s1 == N_NODES) g_row_ptr[N_NODES] = running;
}

__global__ void scatter_kernel(const int* __restrict__ rows,
                               const int* __restrict__ cols,
                               const float* __restrict__ vals,
                               int nE) {
    int e = blockIdx.x * blockDim.x + threadIdx.x;
    if (e >= nE) return;
    int r = rows[e];
    int pos = atomicAdd(&g_cursor[r], 1);
    long long pk = ((long long)__float_as_int(vals[e]) << 32) | (unsigned int)cols[e];
    g_edges[pos] = pk;
}

// ---------------------------------------------------------------------------
// GEMM1 (tf32 tensor): h0[M,128] = x[M,256] @ W1[256,128], fp16 store.
// Block 128x128, K-chunks of 32. 8 warps; warp tile 64x32 (4x4 m16n8k8 tiles).
// ---------------------------------------------------------------------------
__device__ __forceinline__ unsigned f2tf32(float f) {
    unsigned u;
    asm("cvt.rna.tf32.f32 %0, %1;" : "=r"(u) : "f"(f));
    return u;
}

__global__ __launch_bounds__(256) void gemm1_tf32_kernel(const float* __restrict__ X,
                                                         const float* __restrict__ W1) {
    __shared__ unsigned As[128][36];   // A[m][k], pad 36 -> conflict-free frag loads
    __shared__ unsigned Bs[32][132];   // B[k][n], pad 132

    const int tid  = threadIdx.x;
    const int lane = tid & 31;
    const int warp = tid >> 5;
    const int warpM = warp >> 2;       // 0..1 (64 rows each)
    const int warpN = warp & 3;        // 0..3 (32 cols each)
    const int gid = lane >> 2;         // 0..7
    const int tig = lane & 3;          // 0..3
    const int m0 = blockIdx.x * 128;

    float acc[4][4][4];                // [mt][nt][reg]
#pragma unroll
    for (int a = 0; a < 4; a++)
#pragma unroll
        for (int b = 0; b < 4; b++)
#pragma unroll
            for (int c = 0; c < 4; c++) acc[a][b][c] = 0.f;

    for (int kc = 0; kc < IN_F; kc += 32) {
        // Fill As: 128x32 floats = 1024 float4; 4 per thread; convert to tf32.
#pragma unroll
        for (int i = tid; i < 1024; i += 256) {
            int r  = i >> 3;           // 0..127
            int c4 = (i & 7) * 4;      // 0..28
            int gm = m0 + r;
            float4 v = make_float4(0.f, 0.f, 0.f, 0.f);
            if (gm < N_NODES)
                v = *(const float4*)(X + (size_t)gm * IN_F + kc + c4);
            As[r][c4 + 0] = f2tf32(v.x);
            As[r][c4 + 1] = f2tf32(v.y);
            As[r][c4 + 2] = f2tf32(v.z);
            As[r][c4 + 3] = f2tf32(v.w);
        }
        // Fill Bs: 32x128 floats = 1024 float4; 4 per thread.
#pragma unroll
        for (int i = tid; i < 1024; i += 256) {
            int r  = i >> 5;           // 0..31
            int c4 = (i & 31) * 4;     // 0..124
            float4 v = *(const float4*)(W1 + (size_t)(kc + r) * HID_F + c4);
            Bs[r][c4 + 0] = f2tf32(v.x);
            Bs[r][c4 + 1] = f2tf32(v.y);
            Bs[r][c4 + 2] = f2tf32(v.z);
            Bs[r][c4 + 3] = f2tf32(v.w);
        }
        __syncthreads();

#pragma unroll
        for (int ks = 0; ks < 4; ks++) {
            const int k = ks * 8;
            unsigned afrag[4][4];
#pragma unroll
            for (int mt = 0; mt < 4; mt++) {
                int rm = warpM * 64 + mt * 16;
                afrag[mt][0] = As[rm + gid][k + tig];
                afrag[mt][1] = As[rm + gid + 8][k + tig];
                afrag[mt][2] = As[rm + gid][k + tig + 4];
                afrag[mt][3] = As[rm + gid + 8][k + tig + 4];
            }
            unsigned bfrag[4][2];
#pragma unroll
            for (int nt = 0; nt < 4; nt++) {
                int nb = warpN * 32 + nt * 8;
                bfrag[nt][0] = Bs[k + tig][nb + gid];
                bfrag[nt][1] = Bs[k + tig + 4][nb + gid];
            }
#pragma unroll
            for (int mt = 0; mt < 4; mt++)
#pragma unroll
                for (int nt = 0; nt < 4; nt++) {
                    asm volatile(
                        "mma.sync.aligned.m16n8k8.row.col.f32.tf32.tf32.f32 "
                        "{%0,%1,%2,%3}, {%4,%5,%6,%7}, {%8,%9}, {%0,%1,%2,%3};"
                        : "+f"(acc[mt][nt][0]), "+f"(acc[mt][nt][1]),
                          "+f"(acc[mt][nt][2]), "+f"(acc[mt][nt][3])
                        : "r"(afrag[mt][0]), "r"(afrag[mt][1]),
                          "r"(afrag[mt][2]), "r"(afrag[mt][3]),
                          "r"(bfrag[nt][0]), "r"(bfrag[nt][1]));
                }
        }
        __syncthreads();
    }

    // Epilogue: D frag (16x8): c0=(gid,2tig), c1=(gid,2tig+1), c2/3=(gid+8,..)
#pragma unroll
    for (int mt = 0; mt < 4; mt++) {
#pragma unroll
        for (int nt = 0; nt < 4; nt++) {
            int col = warpN * 32 + nt * 8 + 2 * tig;
            int r0 = m0 + warpM * 64 + mt * 16 + gid;
            int r1 = r0 + 8;
            if (r0 < N_NODES) {
                __half2 h = __floats2half2_rn(acc[mt][nt][0], acc[mt][nt][1]);
                *(__half2*)(g_h0h + (size_t)r0 * HID_F + col) = h;
            }
            if (r1 < N_NODES) {
                __half2 h = __floats2half2_rn(acc[mt][nt][2], acc[mt][nt][3]);
                *(__half2*)(g_h0h + (size_t)r1 * HID_F + col) = h;
            }
        }
    }
}

// ---------------------------------------------------------------------------
// SpMM1 gather (F=128, fp16 payload): h1[r] = sum_e val[e] * h0[col[e]]
// ---------------------------------------------------------------------------
__device__ __forceinline__ void fma_h4(float4& acc, uint2 m, float v) {
    float2 f0 = __half22float2(*(__half2*)&m.x);
    float2 f1 = __half22float2(*(__half2*)&m.y);
    acc.x = fmaf(f0.x, v, acc.x);
    acc.y = fmaf(f0.y, v, acc.y);
    acc.z = fmaf(f1.x, v, acc.z);
    acc.w = fmaf(f1.y, v, acc.w);
}

__global__ __launch_bounds__(256) void spmm128_csr_kernel() {
    int row = blockIdx.x * 8 + (threadIdx.x >> 5);
    if (row >= N_NODES) return;
    int lane = threadIdx.x & 31;

    int e  = __ldg(&g_row_ptr[row]);
    int e1 = __ldg(&g_row_ptr[row + 1]);

    float4 acc = make_float4(0.f, 0.f, 0.f, 0.f);

    for (; e + 4 <= e1; e += 4) {
        long long p0 = __ldg(&g_edges[e + 0]);
        long long p1 = __ldg(&g_edges[e + 1]);
        long long p2 = __ldg(&g_edges[e + 2]);
        long long p3 = __ldg(&g_edges[e + 3]);
        uint2 m0 = *((const uint2*)(g_h0h + (size_t)(unsigned int)(p0 & 0xffffffffLL) * HID_F) + lane);
        uint2 m1 = *((const uint2*)(g_h0h + (size_t)(unsigned int)(p1 & 0xffffffffLL) * HID_F) + lane);
        uint2 m2 = *((const uint2*)(g_h0h + (size_t)(unsigned int)(p2 & 0xffffffffLL) * HID_F) + lane);
        uint2 m3 = *((const uint2*)(g_h0h + (size_t)(unsigned int)(p3 & 0xffffffffLL) * HID_F) + lane);
        fma_h4(acc, m0, __int_as_float((int)(p0 >> 32)));
        fma_h4(acc, m1, __int_as_float((int)(p1 >> 32)));
        fma_h4(acc, m2, __int_as_float((int)(p2 >> 32)));
        fma_h4(acc, m3, __int_as_float((int)(p3 >> 32)));
    }
    for (; e < e1; e++) {
        long long pk = __ldg(&g_edges[e]);
        int c  = (int)(unsigned int)(pk & 0xffffffffLL);
        uint2 m = *((const uint2*)(g_h0h + (size_t)c * HID_F) + lane);
        fma_h4(acc, m, __int_as_float((int)(pk >> 32)));
    }
    *((float4*)(g_h1 + (size_t)row * HID_F) + lane) = acc;
}

// ---------------------------------------------------------------------------
// GEMM2: g_h2h[M,32] = fp16( relu(g_h1)[M,128] @ W2[128,32] )
// ---------------------------------------------------------------------------
__global__ __launch_bounds__(256) void gemm2_kernel(const float* __restrict__ W2) {
    __shared__ float Ws[HID_F * OUT_F];
    for (int i = threadIdx.x; i < HID_F * OUT_F; i += 256) Ws[i] = W2[i];
    __syncthreads();

    int r = blockIdx.x * 256 + threadIdx.x;
    if (r >= N_NODES) return;

    float acc[OUT_F];
#pragma unroll
    for (int n = 0; n < OUT_F; n++) acc[n] = 0.f;

    const float4* hp = (const float4*)(g_h1 + (size_t)r * HID_F);
#pragma unroll 4
    for (int k4 = 0; k4 < HID_F / 4; k4++) {
        float4 h = hp[k4];
        h.x = fmaxf(h.x, 0.f);
        h.y = fmaxf(h.y, 0.f);
        h.z = fmaxf(h.z, 0.f);
        h.w = fmaxf(h.w, 0.f);
        int k = k4 * 4;
        float hh[4] = {h.x, h.y, h.z, h.w};
#pragma unroll
        for (int dk = 0; dk < 4; dk++) {
#pragma unroll
            for (int n = 0; n < OUT_F; n += 4) {
                float4 w = *(const float4*)&Ws[(k + dk) * OUT_F + n];
                acc[n + 0] = fmaf(hh[dk], w.x, acc[n + 0]);
                acc[n + 1] = fmaf(hh[dk], w.y, acc[n + 1]);
                acc[n + 2] = fmaf(hh[dk], w.z, acc[n + 2]);
                acc[n + 3] = fmaf(hh[dk], w.w, acc[n + 3]);
            }
        }
    }

    __half2 hb[OUT_F / 2];
#pragma unroll
    for (int n = 0; n < OUT_F / 2; n++)
        hb[n] = __floats2half2_rn(acc[2 * n], acc[2 * n + 1]);
    uint4* op = (uint4*)(g_h2h + (size_t)r * OUT_F);
#pragma unroll
    for (int q = 0; q < 4; q++)
        op[q] = ((uint4*)hb)[q];
}

// ---------------------------------------------------------------------------
// SpMM2 gather (F=32, fp16 payload)
// ---------------------------------------------------------------------------
__global__ __launch_bounds__(256) void spmm32_csr_kernel(float* __restrict__ out) {
    int row = blockIdx.x * 32 + (threadIdx.x >> 3);
    if (row >= N_NODES) return;
    int lane = threadIdx.x & 7;

    int e  = __ldg(&g_row_ptr[row]);
    int e1 = __ldg(&g_row_ptr[row + 1]);

    float4 acc = make_float4(0.f, 0.f, 0.f, 0.f);

    for (; e + 4 <= e1; e += 4) {
        long long p0 = __ldg(&g_edges[e + 0]);
        long long p1 = __ldg(&g_edges[e + 1]);
        long long p2 = __ldg(&g_edges[e + 2]);
        long long p3 = __ldg(&g_edges[e + 3]);
        uint2 m0 = *((const uint2*)(g_h2h + (size_t)(unsigned int)(p0 & 0xffffffffLL) * OUT_F) + lane);
        uint2 m1 = *((const uint2*)(g_h2h + (size_t)(unsigned int)(p1 & 0xffffffffLL) * OUT_F) + lane);
        uint2 m2 = *((const uint2*)(g_h2h + (size_t)(unsigned int)(p2 & 0xffffffffLL) * OUT_F) + lane);
        uint2 m3 = *((const uint2*)(g_h2h + (size_t)(unsigned int)(p3 & 0xffffffffLL) * OUT_F) + lane);
        fma_h4(acc, m0, __int_as_float((int)(p0 >> 32)));
        fma_h4(acc, m1, __int_as_float((int)(p1 >> 32)));
        fma_h4(acc, m2, __int_as_float((int)(p2 >> 32)));
        fma_h4(acc, m3, __int_as_float((int)(p3 >> 32)));
    }
    for (; e < e1; e++) {
        long long pk = __ldg(&g_edges[e]);
        int c  = (int)(unsigned int)(pk & 0xffffffffLL);
        uint2 m = *((const uint2*)(g_h2h + (size_t)c * OUT_F) + lane);
        fma_h4(acc, m, __int_as_float((int)(pk >> 32)));
    }
    *((float4*)(out + (size_t)row * OUT_F) + lane) = acc;
}

// ---------------------------------------------------------------------------
// Launch
// Inputs (metadata order): x, adj_rows, adj_cols, adj_vals, W1, W2
// ---------------------------------------------------------------------------
extern "C" void kernel_launch(void* const* d_in, const int* in_sizes, int n_in,
                              void* d_out, int out_size) {
    const float* x    = (const float*)d_in[0];
    const int*   rows = (const int*)d_in[1];
    const int*   cols = (const int*)d_in[2];
    const float* vals = (const float*)d_in[3];
    const float* W1   = (const float*)d_in[4];
    const float* W2   = (const float*)d_in[5];
    float* out = (float*)d_out;

    const int nE = in_sizes[1];

    // --- CSR build ---
    zero_counts_kernel<<<(N_NODES + 255) / 256, 256>>>();
    hist_kernel<<<(nE / 4 + 255) / 256, 256>>>(rows, nE);
    scan_kernel<<<1, SCAN_T>>>();
    scatter_kernel<<<(nE + 255) / 256, 256>>>(rows, cols, vals, nE);

    // GEMM1 (tf32 tensor): x @ W1 -> h0 (fp16 store)
    gemm1_tf32_kernel<<<(N_NODES + 127) / 128, 256>>>(x, W1);

    // SpMM1: h1 = A_hat @ h0  (fp16 gather, fp32 accum)
    spmm128_csr_kernel<<<(N_NODES + 7) / 8, 256>>>();

    // GEMM2: h2 = relu(h1) @ W2 (fp16 store)
    gemm2_kernel<<<(N_NODES + 255) / 256, 256>>>(W2);

    // SpMM2: out = A_hat @ h2  (fp16 gather, fp32 accum)
    spmm32_csr_kernel<<<(N_NODES + 31) / 32, 256>>>(out);
}